// round 13
// baseline (speedup 1.0000x reference)
#include <cuda_runtime.h>
#include <cuda_bf16.h>
#include <math.h>
#include <stdint.h>

#define B_   16
#define L_   18
#define SQ_  256
#define H_   2560
#define R_   256
#define D_   2048
#define C_   32
#define TOPK_ 16

#define NCHK 80
#define A_CHUNK_BYTES 6144    // 128 rows x 48B (32B int8 data + pad)
#define W_CHUNK_BYTES 3072    // 64 rows x 48B
#define A_TILE_STRIDE (NCHK * A_CHUNK_BYTES)
#define W_TILE_STRIDE (NCHK * W_CHUNK_BYTES)
#define MAXCAND (B_ * L_ * SQ_ * R_)

// int8 2-err margin: sigma_dot ~ 3e-4*||a||*||w||; 0.0045 ~ 10 sigma on 2-err
#define MARGIN_COEF 0.0045f

__device__ float g_qpart[2 * B_ * L_ * R_];
__device__ unsigned g_qmax[B_ * L_ * R_];
__device__ float g_qvec[B_ * L_ * R_];
__device__ float g_sims[B_ * D_ * L_];
__device__ float g_sa[B_ * L_ * 2 * 128];       // per A-row int8 scale
__device__ float g_sb[L_ * R_];                 // per W-row int8 scale
__device__ float g_anorm_tile[B_ * L_ * 2];     // max row L2 norm per tile
__device__ float g_wnorm[L_ * R_];              // per W-row L2 norm
__device__ int   g_ncand;
__device__ int   g_nc2;
__device__ int   g_cand[MAXCAND];
__device__ float g_cval[MAXCAND];
__device__ int   g_cand2[MAXCAND];
__device__ __align__(16) uint8_t g_apack[B_ * L_ * 2 * A_TILE_STRIDE];
__device__ __align__(16) uint8_t g_wpack[L_ * 4 * W_TILE_STRIDE];

// ---------------- helpers ----------------
__device__ __forceinline__ uint32_t smem_u32(const void* p) {
    uint32_t a;
    asm("{ .reg .u64 t; cvta.to.shared.u64 t, %1; cvt.u32.u64 %0, t; }" : "=r"(a) : "l"(p));
    return a;
}
#define MBAR_INIT(a, c) asm volatile("mbarrier.init.shared.b64 [%0], %1;" :: "r"(a), "r"(c) : "memory")
#define MBAR_EXPECT_TX(a, n) asm volatile("mbarrier.arrive.expect_tx.shared.b64 _, [%0], %1;" :: "r"(a), "r"(n) : "memory")
#define MBAR_WAIT(a, par) do {                                                  \
    uint32_t _m=(a), _p=(par), _d;                                              \
    asm volatile("{\n\t.reg .pred p;\n\t"                                       \
      "mbarrier.try_wait.parity.acquire.cta.shared::cta.b64 p, [%1], %2;\n\t"   \
      "selp.b32 %0,1,0,p;\n\t}" : "=r"(_d) : "r"(_m), "r"(_p) : "memory");      \
    if (!_d) { asm volatile("{\n\t.reg .pred P1;\n\tW_%=:\n\t"                  \
      "mbarrier.try_wait.parity.acquire.cta.shared::cta.b64 P1, [%0], %1, 0x989680;\n\t" \
      "@P1 bra.uni WD_%=;\n\tbra.uni W_%=;\n\tWD_%=:\n\t}" :: "r"(_m), "r"(_p) : "memory"); } \
} while (0)
#define BULK_LD(dst, src, sz, mb) \
    asm volatile("cp.async.bulk.shared::cluster.global.mbarrier::complete_tx::bytes [%0], [%1], %2, [%3];" \
                 :: "r"(dst), "l"(src), "r"(sz), "r"(mb) : "memory")

__device__ __forceinline__ void ldm_x4(uint32_t a, uint32_t* r) {
    asm volatile("ldmatrix.sync.aligned.m8n8.x4.shared.b16 {%0,%1,%2,%3}, [%4];"
        : "=r"(r[0]), "=r"(r[1]), "=r"(r[2]), "=r"(r[3]) : "r"(a));
}
__device__ __forceinline__ void imma16832(int* c, const uint32_t* a, const uint32_t* b) {
    asm volatile("mma.sync.aligned.m16n8k32.row.col.s32.s8.s8.s32 "
        "{%0,%1,%2,%3}, {%4,%5,%6,%7}, {%8,%9}, {%0,%1,%2,%3};"
        : "+r"(c[0]), "+r"(c[1]), "+r"(c[2]), "+r"(c[3])
        : "r"(a[0]), "r"(a[1]), "r"(a[2]), "r"(a[3]), "r"(b[0]), "r"(b[1]));
}
__device__ __forceinline__ unsigned enc_f(float f) {
    unsigned u = __float_as_uint(f);
    return (u & 0x80000000u) ? ~u : (u | 0x80000000u);
}
__device__ __forceinline__ float dec_f(unsigned u) {
    unsigned v = (u & 0x80000000u) ? (u & 0x7fffffffu) : ~u;
    return __uint_as_float(v);
}

#define OB1 6144
#define STG_ 9216
#define NSTAGE 4
#define QP_DSM (NSTAGE * STG_)

// ---------------- pack kernels: fp32 -> int8 single plane + scales/norms ----
union Pk16 { uint4 u; int8_t b[16]; };

__device__ __forceinline__ void quant16(const float* __restrict__ src, float inv_sa,
                                        Pk16& p1) {
#pragma unroll
    for (int i = 0; i < 16; i++) {
        float q1 = rintf(src[i] * inv_sa);
        p1.b[i] = (int8_t)(int)fminf(fmaxf(q1, -127.0f), 127.0f);
    }
}

// 576 blocks x 256 thr: tile = pair*2+mt, 128 rows, 2 thr/row
__global__ void pack_a_kernel(const float* __restrict__ q_hs) {
    const int tile = blockIdx.x;
    const int t = threadIdx.x;
    const int row = t >> 1, h = t & 1;
    if ((tile & 1) == 0) g_qmax[(tile >> 1) * R_ + t] = enc_f(-INFINITY);
    const float* src = q_hs + ((size_t)tile * 128 + row) * H_;
    const float4* p4 = (const float4*)src;
    float m = 0.0f, nrm = 0.0f;
    for (int k = 0; k < 320; k++) {
        float4 v = p4[h + 2 * k];
        m = fmaxf(m, fmaxf(fmaxf(fabsf(v.x), fabsf(v.y)), fmaxf(fabsf(v.z), fabsf(v.w))));
        nrm += v.x*v.x + v.y*v.y + v.z*v.z + v.w*v.w;
    }
    m = fmaxf(m, __shfl_xor_sync(0xffffffffu, m, 1));
    nrm += __shfl_xor_sync(0xffffffffu, nrm, 1);
    const float sa = fmaxf(m, 1e-20f) / 127.0f;
    const float inv = 1.0f / sa;
    if (h == 0) g_sa[tile * 128 + row] = sa;

    __shared__ float sm[256];
    sm[t] = nrm;
    __syncthreads();
    for (int s = 128; s > 0; s >>= 1) {
        if (t < s) sm[t] = fmaxf(sm[t], sm[t + s]);
        __syncthreads();
    }
    if (t == 0) g_anorm_tile[tile] = sqrtf(sm[0]);

    uint8_t* dst = g_apack + (size_t)tile * A_TILE_STRIDE;
    float buf[16];
    for (int c = 0; c < NCHK; c++) {
        const float* s = src + c * 32 + h * 16;
#pragma unroll
        for (int i = 0; i < 4; i++) {
            float4 v = ((const float4*)s)[i];
            buf[i*4+0] = v.x; buf[i*4+1] = v.y; buf[i*4+2] = v.z; buf[i*4+3] = v.w;
        }
        Pk16 p1;
        quant16(buf, inv, p1);
        *(uint4*)(dst + c * A_CHUNK_BYTES + row * 48 + h * 16) = p1.u;
    }
}

// 72 blocks x 128 thr: tile = l*4+nt, 64 rows, 2 thr/row
__global__ void pack_w_kernel(const float* __restrict__ w_q) {
    const int tile = blockIdx.x;
    const int l = tile >> 2, nt = tile & 3;
    const int t = threadIdx.x;
    const int row = t >> 1, h = t & 1;
    if (tile == 0 && t == 0) { g_ncand = 0; g_nc2 = 0; }
    const float* src = w_q + ((size_t)(l * R_ + nt * 64 + row)) * H_;
    const float4* p4 = (const float4*)src;
    float m = 0.0f, nrm = 0.0f;
    for (int k = 0; k < 320; k++) {
        float4 v = p4[h + 2 * k];
        m = fmaxf(m, fmaxf(fmaxf(fabsf(v.x), fabsf(v.y)), fmaxf(fabsf(v.z), fabsf(v.w))));
        nrm += v.x*v.x + v.y*v.y + v.z*v.z + v.w*v.w;
    }
    m = fmaxf(m, __shfl_xor_sync(0xffffffffu, m, 1));
    nrm += __shfl_xor_sync(0xffffffffu, nrm, 1);
    const float sb = fmaxf(m, 1e-20f) / 127.0f;
    const float inv = 1.0f / sb;
    if (h == 0) {
        g_sb[l * R_ + nt * 64 + row] = sb;
        g_wnorm[l * R_ + nt * 64 + row] = sqrtf(nrm);
    }

    uint8_t* dst = g_wpack + (size_t)tile * W_TILE_STRIDE;
    float buf[16];
    for (int c = 0; c < NCHK; c++) {
        const float* s = src + c * 32 + h * 16;
#pragma unroll
        for (int i = 0; i < 4; i++) {
            float4 v = ((const float4*)s)[i];
            buf[i*4+0] = v.x; buf[i*4+1] = v.y; buf[i*4+2] = v.z; buf[i*4+3] = v.w;
        }
        Pk16 p1;
        quant16(buf, inv, p1);
        *(uint4*)(dst + c * W_CHUNK_BYTES + row * 48 + h * 16) = p1.u;
    }
}

// ---------------- int8 IMMA GEMM + scaled max-pool + candidate emission -----
// block 128(M) x 64(N); 8 warps 4(m)x2(n); warp tile 32x32; k-chunk 32.
__global__ void __launch_bounds__(256, 2) qproj_mma() {
    extern __shared__ char dsm[];
    __shared__ float sred[4][64];
    __shared__ uint64_t mbars[NSTAGE];

    const uint32_t sb_ = smem_u32(dsm);
    const int mt = blockIdx.x & 1;
    const int nt = (blockIdx.x >> 1) & 3;
    const int pair = blockIdx.y;
    const int l = pair % L_;

    const int tid = threadIdx.x;
    const int wid = tid >> 5;
    const int lane = tid & 31;
    const int warp_m = wid >> 1;   // 0..3
    const int warp_n = wid & 1;    // 0..1

    const int tile_a = pair * 2 + mt;
    const int tile_w = l * 4 + nt;
    const uint8_t* Asrc = g_apack + (size_t)tile_a * A_TILE_STRIDE;
    const uint8_t* Wsrc = g_wpack + (size_t)tile_w * W_TILE_STRIDE;

    const uint32_t mb0 = smem_u32(&mbars[0]);
    if (tid == 0) {
#pragma unroll
        for (int i = 0; i < NSTAGE; i++) MBAR_INIT(mb0 + i * 8, 1);
    }
    __syncthreads();

#define REFILL(t, s)                                                           \
    do {                                                                       \
        if (tid == 0) {                                                        \
            const uint32_t _mb = mb0 + (s) * 8;                                \
            MBAR_EXPECT_TX(_mb, STG_);                                         \
            BULK_LD(sb_ + (s) * STG_,       Asrc + (size_t)(t) * A_CHUNK_BYTES, \
                    A_CHUNK_BYTES, _mb);                                       \
            BULK_LD(sb_ + (s) * STG_ + OB1, Wsrc + (size_t)(t) * W_CHUNK_BYTES, \
                    W_CHUNK_BYTES, _mb);                                       \
        }                                                                      \
    } while (0)

    REFILL(0, 0); REFILL(1, 1); REFILL(2, 2); REFILL(3, 3);

    int acc0[2][4][4];
#pragma unroll
    for (int m = 0; m < 2; m++)
#pragma unroll
        for (int n = 0; n < 4; n++)
#pragma unroll
            for (int r = 0; r < 4; r++) acc0[m][n][r] = 0;

    const uint32_t laneA = ((lane & 7) + ((lane >> 3) & 1) * 8) * 48 + ((lane >> 4) & 1) * 16;
    const uint32_t laneB = ((lane & 7) + ((lane >> 4) & 1) * 8) * 48 + ((lane >> 3) & 1) * 16;
    const uint32_t aRowOff = (uint32_t)(warp_m * 32) * 48;
    const uint32_t bRowOff = (uint32_t)(warp_n * 32) * 48;

    int s = 0, ph = 0;
    for (int t = 0; t < NCHK; t++) {
        MBAR_WAIT(mb0 + s * 8, ph);
        const uint32_t stg = sb_ + s * STG_;

        uint32_t a1[2][4], b1[2][4];
#pragma unroll
        for (int m = 0; m < 2; m++)
            ldm_x4(stg + aRowOff + (uint32_t)(m * 16) * 48 + laneA, a1[m]);
#pragma unroll
        for (int j = 0; j < 2; j++)
            ldm_x4(stg + OB1 + bRowOff + (uint32_t)(j * 16) * 48 + laneB, b1[j]);
#pragma unroll
        for (int m = 0; m < 2; m++)
#pragma unroll
            for (int n = 0; n < 4; n++)
                imma16832(acc0[m][n], a1[m], &b1[n >> 1][(n & 1) * 2]);

        __syncthreads();
        if (t + NSTAGE < NCHK) REFILL(t + NSTAGE, s);
        if (++s == NSTAGE) { s = 0; ph ^= 1; }
    }

    // scaled values
    float sa0[2], sa1[2], sb0[4], sb1[4];
#pragma unroll
    for (int m = 0; m < 2; m++) {
        const int r0 = warp_m * 32 + m * 16 + (lane >> 2);
        sa0[m] = g_sa[tile_a * 128 + r0];
        sa1[m] = g_sa[tile_a * 128 + r0 + 8];
    }
#pragma unroll
    for (int n = 0; n < 4; n++) {
        const int c0 = nt * 64 + warp_n * 32 + n * 8 + (lane & 3) * 2;
        sb0[n] = g_sb[l * R_ + c0];
        sb1[n] = g_sb[l * R_ + c0 + 1];
    }
    float vals[2][4][4];
#pragma unroll
    for (int m = 0; m < 2; m++)
#pragma unroll
        for (int n = 0; n < 4; n++) {
            vals[m][n][0] = (float)acc0[m][n][0] * sa0[m] * sb0[n];
            vals[m][n][1] = (float)acc0[m][n][1] * sa0[m] * sb1[n];
            vals[m][n][2] = (float)acc0[m][n][2] * sa1[m] * sb0[n];
            vals[m][n][3] = (float)acc0[m][n][3] * sa1[m] * sb1[n];
        }

    // block column maxes
    float cm[4][2];
#pragma unroll
    for (int n = 0; n < 4; n++) { cm[n][0] = -INFINITY; cm[n][1] = -INFINITY; }
#pragma unroll
    for (int m = 0; m < 2; m++)
#pragma unroll
        for (int n = 0; n < 4; n++) {
            cm[n][0] = fmaxf(cm[n][0], fmaxf(vals[m][n][0], vals[m][n][2]));
            cm[n][1] = fmaxf(cm[n][1], fmaxf(vals[m][n][1], vals[m][n][3]));
        }
#pragma unroll
    for (int n = 0; n < 4; n++)
#pragma unroll
        for (int j = 0; j < 2; j++) {
#pragma unroll
            for (int off = 4; off < 32; off <<= 1)
                cm[n][j] = fmaxf(cm[n][j], __shfl_xor_sync(0xffffffffu, cm[n][j], off));
        }
    if (lane < 4) {
#pragma unroll
        for (int n = 0; n < 4; n++) {
            sred[warp_m][warp_n * 32 + n * 8 + lane * 2 + 0] = cm[n][0];
            sred[warp_m][warp_n * 32 + n * 8 + lane * 2 + 1] = cm[n][1];
        }
    }
    __syncthreads();
    if (tid < 64) {
        float m = fmaxf(fmaxf(sred[0][tid], sred[1][tid]),
                        fmaxf(sred[2][tid], sred[3][tid]));
        g_qpart[((size_t)pair * 2 + mt) * R_ + nt * 64 + tid] = m;
        sred[0][tid] = m;   // block col max for emission
    }
    __syncthreads();

    // candidate emission vs block-local threshold (superset of global)
    const float an = g_anorm_tile[tile_a];
    float thr[4][2];
#pragma unroll
    for (int n = 0; n < 4; n++) {
#pragma unroll
        for (int j = 0; j < 2; j++) {
            const int c = warp_n * 32 + n * 8 + (lane & 3) * 2 + j;
            thr[n][j] = sred[0][c] -
                        MARGIN_COEF * an * g_wnorm[l * R_ + nt * 64 + c];
        }
    }
#pragma unroll
    for (int m = 0; m < 2; m++)
#pragma unroll
        for (int n = 0; n < 4; n++)
#pragma unroll
            for (int r = 0; r < 4; r++) {
                const int j = r & 1;
                if (vals[m][n][r] >= thr[n][j]) {
                    const int gs = mt * 128 + warp_m * 32 + m * 16 + (lane >> 2) + ((r >> 1) << 3);
                    const int gr = nt * 64 + warp_n * 32 + n * 8 + (lane & 3) * 2 + j;
                    const int slot = atomicAdd(&g_ncand, 1);
                    g_cand[slot] = (pair << 16) | (gs << 8) | gr;
                    g_cval[slot] = vals[m][n][r];
                }
            }
#undef REFILL
}

// ---------------- filter: prune superset against global threshold ----------
__global__ void cand_filter() {
    const int n = g_ncand;
    for (int i = blockIdx.x * blockDim.x + threadIdx.x; i < n;
         i += gridDim.x * blockDim.x) {
        const int id = g_cand[i];
        const int pair = id >> 16, r = id & 255;
        const int l = pair % L_;
        const float m_r = fmaxf(g_qpart[((size_t)pair * 2 + 0) * R_ + r],
                                g_qpart[((size_t)pair * 2 + 1) * R_ + r]);
        const float an = fmaxf(g_anorm_tile[pair * 2], g_anorm_tile[pair * 2 + 1]);
        const float thr = m_r - MARGIN_COEF * an * g_wnorm[l * R_ + r];
        if (g_cval[i] >= thr) {
            const int slot = atomicAdd(&g_nc2, 1);
            g_cand2[slot] = id;
        }
    }
}

// ---------------- rescue: exact fp32 dot per candidate (warp each) ----------
__global__ void rescue_dot(const float* __restrict__ q_hs,
                           const float* __restrict__ w_q) {
    const int lane = threadIdx.x & 31;
    const int gw = (blockIdx.x * blockDim.x + threadIdx.x) >> 5;
    const int nw = (gridDim.x * blockDim.x) >> 5;
    const int n = g_nc2;
    for (int i = gw; i < n; i += nw) {
        const int id = g_cand2[i];
        const int pair = id >> 16, s = (id >> 8) & 255, r = id & 255;
        const int l = pair % L_;
        const float4* a = (const float4*)(q_hs + ((size_t)pair * 256 + s) * H_);
        const float4* w = (const float4*)(w_q + ((size_t)(l * R_ + r)) * H_);
        float acc = 0.0f;
#pragma unroll 4
        for (int k = lane; k < H_ / 4; k += 32) {
            float4 x = a[k], y = w[k];
            acc += x.x*y.x + x.y*y.y + x.z*y.z + x.w*y.w;
        }
#pragma unroll
        for (int off = 16; off > 0; off >>= 1)
            acc += __shfl_xor_sync(0xffffffffu, acc, off);
        if (lane == 0) atomicMax(&g_qmax[pair * R_ + r], enc_f(acc));
    }
}

// ---------------- normalize ----------------
__global__ void qnorm_kernel() {
    const int row = blockIdx.x;
    const int tid = threadIdx.x;
    float v = dec_f(g_qmax[row * R_ + tid]);
    __shared__ float sm[256];
    sm[tid] = v * v;
    __syncthreads();
    for (int s = 128; s > 0; s >>= 1) {
        if (tid < s) sm[tid] += sm[tid + s];
        __syncthreads();
    }
    float inv = 1.0f / fmaxf(sqrtf(sm[0]), 1e-12f);
    g_qvec[(size_t)row * R_ + tid] = v * inv;
}

// ---------------- doc sims (multi-reduce) ----------------
__global__ void __launch_bounds__(256)
docsim_kernel(const float* __restrict__ doc_keys) {
    const int d = blockIdx.x;
    const int l = blockIdx.y;
    const int tid = threadIdx.x;

    __shared__ float4 qs[B_ * 64];
    for (int i = tid; i < B_ * 64; i += 256) {
        int b = i >> 6, j = i & 63;
        qs[i] = *(const float4*)&g_qvec[((size_t)(b * L_ + l)) * R_ + j * 4];
    }
    __syncthreads();

    const int w = tid >> 5, lane = tid & 31;
    float bmax_l = -INFINITY;

    const float* kb = doc_keys + ((size_t)(d * L_ + l)) * C_ * R_;
    for (int ci = 0; ci < 4; ci++) {
        const int c = w * 4 + ci;
        const float4* kp = (const float4*)(kb + (size_t)c * R_);
        float4 k0 = kp[lane], k1 = kp[lane + 32];
        float n2 = k0.x*k0.x + k0.y*k0.y + k0.z*k0.z + k0.w*k0.w +
                   k1.x*k1.x + k1.y*k1.y + k1.z*k1.z + k1.w*k1.w;
#pragma unroll
        for (int off = 16; off > 0; off >>= 1) n2 += __shfl_xor_sync(0xffffffffu, n2, off);
        const float inv = 1.0f / fmaxf(sqrtf(n2), 1e-12f);

        float p[16];
#pragma unroll
        for (int b = 0; b < 16; b++) {
            float4 q0 = qs[b * 64 + lane], q1 = qs[b * 64 + 32 + lane];
            p[b] = k0.x*q0.x + k0.y*q0.y + k0.z*q0.z + k0.w*q0.w +
                   k1.x*q1.x + k1.y*q1.y + k1.z*q1.z + k1.w*q1.w;
        }
#pragma unroll
        for (int b = 0; b < 16; b++) p[b] += __shfl_xor_sync(0xffffffffu, p[b], 16);
#pragma unroll
        for (int bit = 3; bit >= 0; bit--) {
            const int half = 1 << bit;
            const int sel = (lane >> bit) & 1;
#pragma unroll
            for (int j = 0; j < 8; j++) {
                if (j < half) {
                    float keep = sel ? p[j + half] : p[j];
                    float send = sel ? p[j] : p[j + half];
                    float recv = __shfl_xor_sync(0xffffffffu, send, 1 << bit);
                    p[j] = keep + recv;
                }
            }
        }
        bmax_l = fmaxf(bmax_l, p[0] * inv);
    }

    __shared__ float red[8][16];
    if (lane < 16) red[w][lane] = bmax_l;
    __syncthreads();
    if (tid < 16) {
        float m = red[0][tid];
#pragma unroll
        for (int i = 1; i < 8; i++) m = fmaxf(m, red[i][tid]);
        g_sims[((size_t)(tid * D_ + d)) * L_ + l] = m;
    }
}

// ---------------- top-k ----------------
__global__ void topk_kernel(float* __restrict__ out, int out_size) {
    const int b = blockIdx.x;
    const int tid = threadIdx.x;
    __shared__ float sv[D_];
    for (int i = tid; i < D_; i += 256) {
        const float* p = &g_sims[((size_t)(b * D_ + i)) * L_];
        float ssum = 0.0f;
#pragma unroll
        for (int l = 0; l < L_; l++) ssum += p[l];
        sv[i] = ssum / (float)L_;
    }
    __syncthreads();
    __shared__ float rv[256];
    __shared__ int ri[256];
    for (int k = 0; k < TOPK_; k++) {
        float best = -INFINITY; int bi = 0x7fffffff;
        for (int i = tid; i < D_; i += 256) {
            float v = sv[i];
            if (v > best || (v == best && i < bi)) { best = v; bi = i; }
        }
        rv[tid] = best; ri[tid] = bi;
        __syncthreads();
        for (int s = 128; s > 0; s >>= 1) {
            if (tid < s) {
                float v2 = rv[tid + s]; int i2 = ri[tid + s];
                if (v2 > rv[tid] || (v2 == rv[tid] && i2 < ri[tid])) { rv[tid] = v2; ri[tid] = i2; }
            }
            __syncthreads();
        }
        if (tid == 0) {
            out[b * TOPK_ + k] = rv[0];
            if (out_size >= 2 * B_ * TOPK_) out[B_ * TOPK_ + b * TOPK_ + k] = (float)ri[0];
            sv[ri[0]] = -INFINITY;
        }
        __syncthreads();
    }
}

// ---------------------------------------------------------------------------
extern "C" void kernel_launch(void* const* d_in, const int* in_sizes, int n_in,
                              void* d_out, int out_size) {
    const float* q_hs     = (const float*)d_in[0];
    const float* w_q      = (const float*)d_in[1];
    const float* doc_keys = (const float*)d_in[2];
    (void)in_sizes; (void)n_in;

    cudaFuncSetAttribute(qproj_mma, cudaFuncAttributeMaxDynamicSharedMemorySize, QP_DSM);

    pack_w_kernel<<<L_ * 4, 128>>>(w_q);          // resets counters
    pack_a_kernel<<<B_ * L_ * 2, 256>>>(q_hs);    // inits g_qmax
    dim3 gA(8, B_ * L_);
    qproj_mma<<<gA, 256, QP_DSM>>>();
    cand_filter<<<1024, 256>>>();
    rescue_dot<<<2048, 256>>>(q_hs, w_q);
    qnorm_kernel<<<B_ * L_, 256>>>();
    dim3 gB(D_, L_);
    docsim_kernel<<<gB, 256>>>(doc_keys);
    topk_kernel<<<B_, 256>>>((float*)d_out, out_size);
}

// round 15
// speedup vs baseline: 1.4540x; 1.4540x over previous
#include <cuda_runtime.h>
#include <cuda_bf16.h>
#include <math.h>
#include <stdint.h>

#define B_   16
#define L_   18
#define SQ_  256
#define H_   2560
#define R_   256
#define D_   2048
#define C_   32
#define TOPK_ 16

#define NCHK 80              // H/32
#define CHUNK_BYTES 8192     // 128 rows x 64B bf16
#define TILE_STRIDE (NCHK * CHUNK_BYTES)
#define MAXCAND (B_ * L_ * SQ_ * R_)

__device__ float g_qpart[2 * B_ * L_ * R_];     // approx per-(tile) col maxes
__device__ unsigned g_qmax[B_ * L_ * R_];       // encoded exact col maxes
__device__ float g_qvec[B_ * L_ * R_];
__device__ float g_sims[B_ * D_ * L_];
__device__ float g_anorm_tile[B_ * L_ * 2];
__device__ float g_wnorm[L_ * R_];
__device__ int   g_ncand;                        // raw (superset) count
__device__ int   g_nc2;                          // filtered count
__device__ int   g_cand[MAXCAND];
__device__ float g_cval[MAXCAND];
__device__ int   g_cand2[MAXCAND];
__device__ __align__(16) uint8_t g_apack[B_ * L_ * 2 * TILE_STRIDE];
__device__ __align__(16) uint8_t g_wpack[L_ * 2 * TILE_STRIDE];

// statistical margin: sigma_err ~= 2^-8*||a||*||w||/sqrt(H); margin ~26 sigma
#define MARGIN_COEF 0.002f

// ---------------- helpers ----------------
__device__ __forceinline__ uint32_t smem_u32(const void* p) {
    uint32_t a;
    asm("{ .reg .u64 t; cvta.to.shared.u64 t, %1; cvt.u32.u64 %0, t; }" : "=r"(a) : "l"(p));
    return a;
}
#define MBAR_INIT(a, c) asm volatile("mbarrier.init.shared.b64 [%0], %1;" :: "r"(a), "r"(c) : "memory")
#define MBAR_EXPECT_TX(a, n) asm volatile("mbarrier.arrive.expect_tx.shared.b64 _, [%0], %1;" :: "r"(a), "r"(n) : "memory")
#define MBAR_WAIT(a, par) do {                                                  \
    uint32_t _m=(a), _p=(par), _d;                                              \
    asm volatile("{\n\t.reg .pred p;\n\t"                                       \
      "mbarrier.try_wait.parity.acquire.cta.shared::cta.b64 p, [%1], %2;\n\t"   \
      "selp.b32 %0,1,0,p;\n\t}" : "=r"(_d) : "r"(_m), "r"(_p) : "memory");      \
    if (!_d) { asm volatile("{\n\t.reg .pred P1;\n\tW_%=:\n\t"                  \
      "mbarrier.try_wait.parity.acquire.cta.shared::cta.b64 P1, [%0], %1, 0x989680;\n\t" \
      "@P1 bra.uni WD_%=;\n\tbra.uni W_%=;\n\tWD_%=:\n\t}" :: "r"(_m), "r"(_p) : "memory"); } \
} while (0)
#define BULK_LD(dst, src, sz, mb) \
    asm volatile("cp.async.bulk.shared::cluster.global.mbarrier::complete_tx::bytes [%0], [%1], %2, [%3];" \
                 :: "r"(dst), "l"(src), "r"(sz), "r"(mb) : "memory")

__device__ __forceinline__ void ldm_x4(uint32_t a, uint32_t* r) {
    asm volatile("ldmatrix.sync.aligned.m8n8.x4.shared.b16 {%0,%1,%2,%3}, [%4];"
        : "=r"(r[0]), "=r"(r[1]), "=r"(r[2]), "=r"(r[3]) : "r"(a));
}
__device__ __forceinline__ void mma16816(float* c, const uint32_t* a, const uint32_t* b) {
    asm volatile("mma.sync.aligned.m16n8k16.row.col.f32.bf16.bf16.f32 "
        "{%0,%1,%2,%3}, {%4,%5,%6,%7}, {%8,%9}, {%0,%1,%2,%3};"
        : "+f"(c[0]), "+f"(c[1]), "+f"(c[2]), "+f"(c[3])
        : "r"(a[0]), "r"(a[1]), "r"(a[2]), "r"(a[3]), "r"(b[0]), "r"(b[1]));
}
__device__ __forceinline__ unsigned enc_f(float f) {
    unsigned u = __float_as_uint(f);
    return (u & 0x80000000u) ? ~u : (u | 0x80000000u);
}
__device__ __forceinline__ float dec_f(unsigned u) {
    unsigned v = (u & 0x80000000u) ? (u & 0x7fffffffu) : ~u;
    return __uint_as_float(v);
}

#define OA 0
#define OB 8192
#define STG_ 16384
#define NSTAGE 4
#define QP_DSM (NSTAGE * STG_)

// ---------------- pack kernels: fp32 -> bf16 chunk tiles + L2 norms ---------
__device__ __forceinline__ void pack_half_chunk(const float* __restrict__ s,
                                                uint8_t* __restrict__ dstc,
                                                int h, uint32_t X, float& nrm) {
#pragma unroll
    for (int j = 0; j < 2; j++) {
        float4 a = ((const float4*)s)[j * 2];
        float4 b = ((const float4*)s)[j * 2 + 1];
        nrm += a.x*a.x + a.y*a.y + a.z*a.z + a.w*a.w +
               b.x*b.x + b.y*b.y + b.z*b.z + b.w*b.w;
        __nv_bfloat162 p0{__float2bfloat16_rn(a.x), __float2bfloat16_rn(a.y)};
        __nv_bfloat162 p1{__float2bfloat16_rn(a.z), __float2bfloat16_rn(a.w)};
        __nv_bfloat162 p2{__float2bfloat16_rn(b.x), __float2bfloat16_rn(b.y)};
        __nv_bfloat162 p3{__float2bfloat16_rn(b.z), __float2bfloat16_rn(b.w)};
        uint4 out = make_uint4(*(uint32_t*)&p0, *(uint32_t*)&p1,
                               *(uint32_t*)&p2, *(uint32_t*)&p3);
        const uint32_t g = h * 2 + j;
        *(uint4*)(dstc + (((g ^ X) << 4))) = out;
    }
}

__global__ void pack_a_kernel(const float* __restrict__ q_hs) {
    const int tile = blockIdx.x;
    const int tid = threadIdx.x;
    const int row = tid >> 1, h = tid & 1;
    if ((tile & 1) == 0) g_qmax[(tile >> 1) * R_ + tid] = enc_f(-INFINITY);
    const float* src = q_hs + ((size_t)tile * 128 + row) * H_;
    uint8_t* dst = g_apack + (size_t)tile * TILE_STRIDE + row * 64;
    const uint32_t X = (row >> 1) & 3;
    float nrm = 0.0f;
    for (int c = 0; c < NCHK; c++)
        pack_half_chunk(src + c * 32 + h * 16, dst + (size_t)c * CHUNK_BYTES, h, X, nrm);
    nrm += __shfl_xor_sync(0xffffffffu, nrm, 1);
    __shared__ float sm[256];
    sm[tid] = nrm;
    __syncthreads();
    for (int s = 128; s > 0; s >>= 1) {
        if (tid < s) sm[tid] = fmaxf(sm[tid], sm[tid + s]);
        __syncthreads();
    }
    if (tid == 0) g_anorm_tile[tile] = sqrtf(sm[0]);
}

__global__ void pack_w_kernel(const float* __restrict__ w_q) {
    const int tile = blockIdx.x;
    const int l = tile >> 1, nt = tile & 1;
    const int tid = threadIdx.x;
    const int row = tid >> 1, h = tid & 1;
    if (tile == 0 && tid == 0) { g_ncand = 0; g_nc2 = 0; }
    const float* src = w_q + ((size_t)(l * R_ + nt * 128 + row)) * H_;
    uint8_t* dst = g_wpack + (size_t)tile * TILE_STRIDE + row * 64;
    const uint32_t X = (row >> 1) & 3;
    float nrm = 0.0f;
    for (int c = 0; c < NCHK; c++)
        pack_half_chunk(src + c * 32 + h * 16, dst + (size_t)c * CHUNK_BYTES, h, X, nrm);
    nrm += __shfl_xor_sync(0xffffffffu, nrm, 1);
    if (h == 0) g_wnorm[l * R_ + nt * 128 + row] = sqrtf(nrm);
}

// ---------------- bf16 GEMM + fused max-pool + fused candidate emission -----
__global__ void __launch_bounds__(256, 2) qproj_mma() {
    extern __shared__ char dsm[];
    __shared__ float sred[2][128];
    __shared__ uint64_t mbars[NSTAGE];

    const uint32_t sb = smem_u32(dsm);
    const int mt = blockIdx.x & 1;
    const int nt = blockIdx.x >> 1;
    const int pair = blockIdx.y;
    const int l = pair % L_;

    const int tid = threadIdx.x;
    const int wid = tid >> 5;
    const int lane = tid & 31;
    const int warp_m = wid >> 2;
    const int warp_n = wid & 3;

    const uint8_t* Asrc = g_apack + (size_t)(pair * 2 + mt) * TILE_STRIDE;
    const uint8_t* Bsrc = g_wpack + (size_t)(l * 2 + nt) * TILE_STRIDE;

    const uint32_t mb0 = smem_u32(&mbars[0]);
    if (tid == 0) {
#pragma unroll
        for (int i = 0; i < NSTAGE; i++) MBAR_INIT(mb0 + i * 8, 1);
    }
    __syncthreads();

#define REFILL(t, s)                                                           \
    do {                                                                       \
        if (tid == 0) {                                                        \
            const uint32_t _mb = mb0 + (s) * 8;                                \
            MBAR_EXPECT_TX(_mb, STG_);                                         \
            BULK_LD(sb + (s) * STG_ + OA, Asrc + (size_t)(t) * CHUNK_BYTES,    \
                    CHUNK_BYTES, _mb);                                         \
            BULK_LD(sb + (s) * STG_ + OB, Bsrc + (size_t)(t) * CHUNK_BYTES,    \
                    CHUNK_BYTES, _mb);                                         \
        }                                                                      \
    } while (0)

    REFILL(0, 0); REFILL(1, 1); REFILL(2, 2); REFILL(3, 3);

    float acc[4][4][4];
#pragma unroll
    for (int m = 0; m < 4; m++)
#pragma unroll
        for (int n = 0; n < 4; n++)
#pragma unroll
            for (int r = 0; r < 4; r++) acc[m][n][r] = 0.0f;

    const uint32_t XA = ((lane & 15) >> 1) & 3;
    const uint32_t rowA = (uint32_t)(warp_m * 64 + (lane & 15)) * 64;
    const uint32_t cAsel = (lane >> 4) & 1;
    const uint32_t XB = ((lane & 7) >> 1) & 3;
    const uint32_t rowB = (uint32_t)(warp_n * 32 + ((lane >> 4) & 1) * 8 + (lane & 7)) * 64;
    const uint32_t cBsel = (lane >> 3) & 1;

    int s = 0, ph = 0;
    for (int t = 0; t < NCHK; t++) {
        MBAR_WAIT(mb0 + s * 8, ph);
        const uint32_t stg = sb + s * STG_;
#pragma unroll
        for (int ks = 0; ks < 2; ks++) {
            const uint32_t colA = (((ks * 2 + cAsel) ^ XA) << 4);
            const uint32_t colB = (((ks * 2 + cBsel) ^ XB) << 4);
            const uint32_t aBase = stg + OA + rowA + colA;
            const uint32_t bBase = stg + OB + rowB + colB;
            uint32_t a[4][4], b[2][4];
#pragma unroll
            for (int m = 0; m < 4; m++) ldm_x4(aBase + m * 1024, a[m]);
#pragma unroll
            for (int p = 0; p < 2; p++) ldm_x4(bBase + p * 1024, b[p]);
#pragma unroll
            for (int m = 0; m < 4; m++)
#pragma unroll
                for (int n = 0; n < 4; n++)
                    mma16816(acc[m][n], a[m], &b[n >> 1][(n & 1) * 2]);
        }
        __syncthreads();
        if (t + NSTAGE < NCHK) REFILL(t + NSTAGE, s);
        if (++s == NSTAGE) { s = 0; ph ^= 1; }
    }

    // block column maxes
#pragma unroll
    for (int n = 0; n < 4; n++) {
        float m0 = -INFINITY, m1 = -INFINITY;
#pragma unroll
        for (int m = 0; m < 4; m++) {
            m0 = fmaxf(m0, fmaxf(acc[m][n][0], acc[m][n][2]));
            m1 = fmaxf(m1, fmaxf(acc[m][n][1], acc[m][n][3]));
        }
#pragma unroll
        for (int off = 4; off < 32; off <<= 1) {
            m0 = fmaxf(m0, __shfl_xor_sync(0xffffffffu, m0, off));
            m1 = fmaxf(m1, __shfl_xor_sync(0xffffffffu, m1, off));
        }
        if (lane < 4) {
            sred[warp_m][warp_n * 32 + n * 8 + lane * 2 + 0] = m0;
            sred[warp_m][warp_n * 32 + n * 8 + lane * 2 + 1] = m1;
        }
    }
    __syncthreads();
    if (tid < 128) {
        g_qpart[((size_t)pair * 2 + mt) * R_ + nt * 128 + tid] =
            fmaxf(sred[0][tid], sred[1][tid]);
    }
    __syncthreads();

    // candidate emission vs block-local threshold (superset of global)
    const float an = g_anorm_tile[pair * 2 + mt];
    float thr[4][2];
#pragma unroll
    for (int n = 0; n < 4; n++) {
#pragma unroll
        for (int j = 0; j < 2; j++) {
            const int c = warp_n * 32 + n * 8 + (lane & 3) * 2 + j;
            const float bm = fmaxf(sred[0][c], sred[1][c]);
            thr[n][j] = bm - MARGIN_COEF * an * g_wnorm[l * R_ + nt * 128 + c];
        }
    }
#pragma unroll
    for (int m = 0; m < 4; m++)
#pragma unroll
        for (int n = 0; n < 4; n++)
#pragma unroll
            for (int r = 0; r < 4; r++) {
                const int j = r & 1;
                if (acc[m][n][r] >= thr[n][j]) {
                    const int sl = warp_m * 64 + m * 16 + (lane >> 2) + ((r >> 1) << 3);
                    const int gs = mt * 128 + sl;
                    const int gr = nt * 128 + warp_n * 32 + n * 8 + (lane & 3) * 2 + j;
                    const int slot = atomicAdd(&g_ncand, 1);
                    g_cand[slot] = (pair << 16) | (gs << 8) | gr;
                    g_cval[slot] = acc[m][n][r];
                }
            }
#undef REFILL
}

// ---------------- filter: prune superset against global threshold ----------
__global__ void cand_filter() {
    const int n = g_ncand;
    for (int i = blockIdx.x * blockDim.x + threadIdx.x; i < n;
         i += gridDim.x * blockDim.x) {
        const int id = g_cand[i];
        const int pair = id >> 16, r = id & 255;
        const int l = pair % L_;
        const float m_r = fmaxf(g_qpart[((size_t)pair * 2 + 0) * R_ + r],
                                g_qpart[((size_t)pair * 2 + 1) * R_ + r]);
        const float an = fmaxf(g_anorm_tile[pair * 2], g_anorm_tile[pair * 2 + 1]);
        const float thr = m_r - MARGIN_COEF * an * g_wnorm[l * R_ + r];
        if (g_cval[i] >= thr) {
            const int slot = atomicAdd(&g_nc2, 1);
            g_cand2[slot] = id;
        }
    }
}

// ---------------- rescue: exact fp32 dot per candidate (warp each) ----------
__global__ void rescue_dot(const float* __restrict__ q_hs,
                           const float* __restrict__ w_q) {
    const int lane = threadIdx.x & 31;
    const int gw = (blockIdx.x * blockDim.x + threadIdx.x) >> 5;
    const int nw = (gridDim.x * blockDim.x) >> 5;
    const int n = g_nc2;
    for (int i = gw; i < n; i += nw) {
        const int id = g_cand2[i];
        const int pair = id >> 16, s = (id >> 8) & 255, r = id & 255;
        const int l = pair % L_;
        const float4* a = (const float4*)(q_hs + ((size_t)pair * 256 + s) * H_);
        const float4* w = (const float4*)(w_q + ((size_t)(l * R_ + r)) * H_);
        float acc = 0.0f;
#pragma unroll 4
        for (int k = lane; k < H_ / 4; k += 32) {
            float4 x = a[k], y = w[k];
            acc += x.x*y.x + x.y*y.y + x.z*y.z + x.w*y.w;
        }
#pragma unroll
        for (int off = 16; off > 0; off >>= 1)
            acc += __shfl_xor_sync(0xffffffffu, acc, off);
        if (lane == 0) atomicMax(&g_qmax[pair * R_ + r], enc_f(acc));
    }
}

// ---------------- normalize ----------------
__global__ void qnorm_kernel() {
    const int row = blockIdx.x;
    const int tid = threadIdx.x;
    float v = dec_f(g_qmax[row * R_ + tid]);
    __shared__ float sm[256];
    sm[tid] = v * v;
    __syncthreads();
    for (int s = 128; s > 0; s >>= 1) {
        if (tid < s) sm[tid] += sm[tid + s];
        __syncthreads();
    }
    float inv = 1.0f / fmaxf(sqrtf(sm[0]), 1e-12f);
    g_qvec[(size_t)row * R_ + tid] = v * inv;
}

// ---------------- doc sims (multi-reduce + chunk prefetch) ----------------
__global__ void __launch_bounds__(256)
docsim_kernel(const float* __restrict__ doc_keys) {
    const int d = blockIdx.x;
    const int l = blockIdx.y;
    const int tid = threadIdx.x;

    __shared__ float4 qs[B_ * 64];
    for (int i = tid; i < B_ * 64; i += 256) {
        int b = i >> 6, j = i & 63;
        qs[i] = *(const float4*)&g_qvec[((size_t)(b * L_ + l)) * R_ + j * 4];
    }
    __syncthreads();

    const int w = tid >> 5, lane = tid & 31;
    float bmax_l = -INFINITY;   // per-lane: b = lane & 15

    const float* kb = doc_keys + ((size_t)(d * L_ + l)) * C_ * R_;
    // prime chunk 0
    const float4* kp0 = (const float4*)(kb + (size_t)(w * 4) * R_);
    float4 k0 = kp0[lane], k1 = kp0[lane + 32];

    for (int ci = 0; ci < 4; ci++) {
        // prefetch next chunk before the dependent reduce chain
        float4 n0, n1;
        if (ci < 3) {
            const float4* np = (const float4*)(kb + (size_t)(w * 4 + ci + 1) * R_);
            n0 = np[lane]; n1 = np[lane + 32];
        }

        float n2 = k0.x*k0.x + k0.y*k0.y + k0.z*k0.z + k0.w*k0.w +
                   k1.x*k1.x + k1.y*k1.y + k1.z*k1.z + k1.w*k1.w;
#pragma unroll
        for (int off = 16; off > 0; off >>= 1) n2 += __shfl_xor_sync(0xffffffffu, n2, off);
        const float inv = 1.0f / fmaxf(sqrtf(n2), 1e-12f);

        float p[16];
#pragma unroll
        for (int b = 0; b < 16; b++) {
            float4 q0 = qs[b * 64 + lane], q1 = qs[b * 64 + 32 + lane];
            p[b] = k0.x*q0.x + k0.y*q0.y + k0.z*q0.z + k0.w*q0.w +
                   k1.x*q1.x + k1.y*q1.y + k1.z*q1.z + k1.w*q1.w;
        }
#pragma unroll
        for (int b = 0; b < 16; b++) p[b] += __shfl_xor_sync(0xffffffffu, p[b], 16);
#pragma unroll
        for (int bit = 3; bit >= 0; bit--) {
            const int half = 1 << bit;
            const int sel = (lane >> bit) & 1;
#pragma unroll
            for (int j = 0; j < 8; j++) {
                if (j < half) {
                    float keep = sel ? p[j + half] : p[j];
                    float send = sel ? p[j] : p[j + half];
                    float recv = __shfl_xor_sync(0xffffffffu, send, 1 << bit);
                    p[j] = keep + recv;
                }
            }
        }
        bmax_l = fmaxf(bmax_l, p[0] * inv);

        if (ci < 3) { k0 = n0; k1 = n1; }
    }

    __shared__ float red[8][16];
    if (lane < 16) red[w][lane] = bmax_l;
    __syncthreads();
    if (tid < 16) {
        float m = red[0][tid];
#pragma unroll
        for (int i = 1; i < 8; i++) m = fmaxf(m, red[i][tid]);
        g_sims[((size_t)(tid * D_ + d)) * L_ + l] = m;
    }
}

// ---------------- top-k ----------------
__global__ void topk_kernel(float* __restrict__ out, int out_size) {
    const int b = blockIdx.x;
    const int tid = threadIdx.x;
    __shared__ float sv[D_];
    for (int i = tid; i < D_; i += 256) {
        const float* p = &g_sims[((size_t)(b * D_ + i)) * L_];
        float ssum = 0.0f;
#pragma unroll
        for (int l = 0; l < L_; l++) ssum += p[l];
        sv[i] = ssum / (float)L_;
    }
    __syncthreads();
    __shared__ float rv[256];
    __shared__ int ri[256];
    for (int k = 0; k < TOPK_; k++) {
        float best = -INFINITY; int bi = 0x7fffffff;
        for (int i = tid; i < D_; i += 256) {
            float v = sv[i];
            if (v > best || (v == best && i < bi)) { best = v; bi = i; }
        }
        rv[tid] = best; ri[tid] = bi;
        __syncthreads();
        for (int s = 128; s > 0; s >>= 1) {
            if (tid < s) {
                float v2 = rv[tid + s]; int i2 = ri[tid + s];
                if (v2 > rv[tid] || (v2 == rv[tid] && i2 < ri[tid])) { rv[tid] = v2; ri[tid] = i2; }
            }
            __syncthreads();
        }
        if (tid == 0) {
            out[b * TOPK_ + k] = rv[0];
            if (out_size >= 2 * B_ * TOPK_) out[B_ * TOPK_ + b * TOPK_ + k] = (float)ri[0];
            sv[ri[0]] = -INFINITY;
        }
        __syncthreads();
    }
}

// ---------------------------------------------------------------------------
extern "C" void kernel_launch(void* const* d_in, const int* in_sizes, int n_in,
                              void* d_out, int out_size) {
    const float* q_hs     = (const float*)d_in[0];
    const float* w_q      = (const float*)d_in[1];
    const float* doc_keys = (const float*)d_in[2];
    (void)in_sizes; (void)n_in;

    cudaFuncSetAttribute(qproj_mma, cudaFuncAttributeMaxDynamicSharedMemorySize, QP_DSM);

    pack_w_kernel<<<L_ * 2, 256>>>(w_q);          // also resets counters
    pack_a_kernel<<<B_ * L_ * 2, 256>>>(q_hs);    // also inits g_qmax
    dim3 gA(4, B_ * L_);
    qproj_mma<<<gA, 256, QP_DSM>>>();
    cand_filter<<<1024, 256>>>();
    rescue_dot<<<2048, 256>>>(q_hs, w_q);
    qnorm_kernel<<<B_ * L_, 256>>>();
    dim3 gB(D_, L_);
    docsim_kernel<<<gB, 256>>>(doc_keys);
    topk_kernel<<<B_, 256>>>((float*)d_out, out_size);
}

// round 16
// speedup vs baseline: 1.4560x; 1.0013x over previous
#include <cuda_runtime.h>
#include <cuda_bf16.h>
#include <math.h>
#include <stdint.h>

#define B_   16
#define L_   18
#define SQ_  256
#define H_   2560
#define R_   256
#define D_   2048
#define C_   32
#define TOPK_ 16

#define NCHK 80              // H/32 packed chunks
#define CHUNK_BYTES 8192     // 128 rows x 64B bf16
#define TILE_STRIDE (NCHK * CHUNK_BYTES)
#define MAXCAND (B_ * L_ * SQ_ * R_)

__device__ float g_qpart[2 * B_ * L_ * R_];
__device__ unsigned g_qmax[B_ * L_ * R_];
__device__ float g_qvec[B_ * L_ * R_];
__device__ float g_sims[B_ * D_ * L_];
__device__ float g_anorm_tile[B_ * L_ * 2];
__device__ float g_wnorm[L_ * R_];
__device__ int   g_ncand;
__device__ int   g_cand[MAXCAND];
__device__ float g_cval[MAXCAND];
__device__ __align__(16) uint8_t g_apack[B_ * L_ * 2 * TILE_STRIDE];
__device__ __align__(16) uint8_t g_wpack[L_ * 2 * TILE_STRIDE];

// statistical margin: sigma_err ~= 2^-8*||a||*||w||/sqrt(H); margin ~26 sigma
#define MARGIN_COEF 0.002f

// ---------------- helpers ----------------
__device__ __forceinline__ uint32_t smem_u32(const void* p) {
    uint32_t a;
    asm("{ .reg .u64 t; cvta.to.shared.u64 t, %1; cvt.u32.u64 %0, t; }" : "=r"(a) : "l"(p));
    return a;
}
#define MBAR_INIT(a, c) asm volatile("mbarrier.init.shared.b64 [%0], %1;" :: "r"(a), "r"(c) : "memory")
#define MBAR_EXPECT_TX(a, n) asm volatile("mbarrier.arrive.expect_tx.shared.b64 _, [%0], %1;" :: "r"(a), "r"(n) : "memory")
#define MBAR_WAIT(a, par) do {                                                  \
    uint32_t _m=(a), _p=(par), _d;                                              \
    asm volatile("{\n\t.reg .pred p;\n\t"                                       \
      "mbarrier.try_wait.parity.acquire.cta.shared::cta.b64 p, [%1], %2;\n\t"   \
      "selp.b32 %0,1,0,p;\n\t}" : "=r"(_d) : "r"(_m), "r"(_p) : "memory");      \
    if (!_d) { asm volatile("{\n\t.reg .pred P1;\n\tW_%=:\n\t"                  \
      "mbarrier.try_wait.parity.acquire.cta.shared::cta.b64 P1, [%0], %1, 0x989680;\n\t" \
      "@P1 bra.uni WD_%=;\n\tbra.uni W_%=;\n\tWD_%=:\n\t}" :: "r"(_m), "r"(_p) : "memory"); } \
} while (0)
#define BULK_LD(dst, src, sz, mb) \
    asm volatile("cp.async.bulk.shared::cluster.global.mbarrier::complete_tx::bytes [%0], [%1], %2, [%3];" \
                 :: "r"(dst), "l"(src), "r"(sz), "r"(mb) : "memory")

__device__ __forceinline__ void ldm_x4(uint32_t a, uint32_t* r) {
    asm volatile("ldmatrix.sync.aligned.m8n8.x4.shared.b16 {%0,%1,%2,%3}, [%4];"
        : "=r"(r[0]), "=r"(r[1]), "=r"(r[2]), "=r"(r[3]) : "r"(a));
}
__device__ __forceinline__ void mma16816(float* c, const uint32_t* a, const uint32_t* b) {
    asm volatile("mma.sync.aligned.m16n8k16.row.col.f32.bf16.bf16.f32 "
        "{%0,%1,%2,%3}, {%4,%5,%6,%7}, {%8,%9}, {%0,%1,%2,%3};"
        : "+f"(c[0]), "+f"(c[1]), "+f"(c[2]), "+f"(c[3])
        : "r"(a[0]), "r"(a[1]), "r"(a[2]), "r"(a[3]), "r"(b[0]), "r"(b[1]));
}
__device__ __forceinline__ unsigned enc_f(float f) {
    unsigned u = __float_as_uint(f);
    return (u & 0x80000000u) ? ~u : (u | 0x80000000u);
}
__device__ __forceinline__ float dec_f(unsigned u) {
    unsigned v = (u & 0x80000000u) ? (u & 0x7fffffffu) : ~u;
    return __uint_as_float(v);
}

// stage = 2 A-chunks (16KB) + 2 B-chunks (16KB) = 32KB; 3 stages = 96KB
#define OA 0
#define OB 16384
#define STG_ 32768
#define NSTAGE 3
#define NMAC 40              // macro chunks of K=64
#define QP_DSM (NSTAGE * STG_)

// ---------------- pack kernels: fp32 -> bf16 chunk tiles + L2 norms ---------
__device__ __forceinline__ void pack_half_chunk(const float* __restrict__ s,
                                                uint8_t* __restrict__ dstc,
                                                int h, uint32_t X, float& nrm) {
#pragma unroll
    for (int j = 0; j < 2; j++) {
        float4 a = ((const float4*)s)[j * 2];
        float4 b = ((const float4*)s)[j * 2 + 1];
        nrm += a.x*a.x + a.y*a.y + a.z*a.z + a.w*a.w +
               b.x*b.x + b.y*b.y + b.z*b.z + b.w*b.w;
        __nv_bfloat162 p0{__float2bfloat16_rn(a.x), __float2bfloat16_rn(a.y)};
        __nv_bfloat162 p1{__float2bfloat16_rn(a.z), __float2bfloat16_rn(a.w)};
        __nv_bfloat162 p2{__float2bfloat16_rn(b.x), __float2bfloat16_rn(b.y)};
        __nv_bfloat162 p3{__float2bfloat16_rn(b.z), __float2bfloat16_rn(b.w)};
        uint4 out = make_uint4(*(uint32_t*)&p0, *(uint32_t*)&p1,
                               *(uint32_t*)&p2, *(uint32_t*)&p3);
        const uint32_t g = h * 2 + j;
        *(uint4*)(dstc + (((g ^ X) << 4))) = out;
    }
}

__global__ void pack_a_kernel(const float* __restrict__ q_hs) {
    const int tile = blockIdx.x;
    const int tid = threadIdx.x;
    const int row = tid >> 1, h = tid & 1;
    if ((tile & 1) == 0) g_qmax[(tile >> 1) * R_ + tid] = enc_f(-INFINITY);
    const float* src = q_hs + ((size_t)tile * 128 + row) * H_;
    uint8_t* dst = g_apack + (size_t)tile * TILE_STRIDE + row * 64;
    const uint32_t X = (row >> 1) & 3;
    float nrm = 0.0f;
    for (int c = 0; c < NCHK; c++)
        pack_half_chunk(src + c * 32 + h * 16, dst + (size_t)c * CHUNK_BYTES, h, X, nrm);
    nrm += __shfl_xor_sync(0xffffffffu, nrm, 1);
    __shared__ float sm[256];
    sm[tid] = nrm;
    __syncthreads();
    for (int s = 128; s > 0; s >>= 1) {
        if (tid < s) sm[tid] = fmaxf(sm[tid], sm[tid + s]);
        __syncthreads();
    }
    if (tid == 0) g_anorm_tile[tile] = sqrtf(sm[0]);
}

__global__ void pack_w_kernel(const float* __restrict__ w_q) {
    const int tile = blockIdx.x;
    const int l = tile >> 1, nt = tile & 1;
    const int tid = threadIdx.x;
    const int row = tid >> 1, h = tid & 1;
    if (tile == 0 && tid == 0) g_ncand = 0;
    const float* src = w_q + ((size_t)(l * R_ + nt * 128 + row)) * H_;
    uint8_t* dst = g_wpack + (size_t)tile * TILE_STRIDE + row * 64;
    const uint32_t X = (row >> 1) & 3;
    float nrm = 0.0f;
    for (int c = 0; c < NCHK; c++)
        pack_half_chunk(src + c * 32 + h * 16, dst + (size_t)c * CHUNK_BYTES, h, X, nrm);
    nrm += __shfl_xor_sync(0xffffffffu, nrm, 1);
    if (h == 0) g_wnorm[l * R_ + nt * 128 + row] = sqrtf(nrm);
}

// ---------------- bf16 GEMM (K-macro 64) + max-pool + candidate emission ----
__global__ void __launch_bounds__(256, 2) qproj_mma() {
    extern __shared__ char dsm[];
    __shared__ float sred[2][128];
    __shared__ uint64_t mbars[NSTAGE];

    const uint32_t sb = smem_u32(dsm);
    const int mt = blockIdx.x & 1;
    const int nt = blockIdx.x >> 1;
    const int pair = blockIdx.y;
    const int l = pair % L_;

    const int tid = threadIdx.x;
    const int wid = tid >> 5;
    const int lane = tid & 31;
    const int warp_m = wid >> 2;
    const int warp_n = wid & 3;

    const uint8_t* Asrc = g_apack + (size_t)(pair * 2 + mt) * TILE_STRIDE;
    const uint8_t* Bsrc = g_wpack + (size_t)(l * 2 + nt) * TILE_STRIDE;

    const uint32_t mb0 = smem_u32(&mbars[0]);
    if (tid == 0) {
#pragma unroll
        for (int i = 0; i < NSTAGE; i++) MBAR_INIT(mb0 + i * 8, 1);
    }
    __syncthreads();

// macro chunk t consumes packed chunks 2t, 2t+1
#define REFILL(t, s)                                                           \
    do {                                                                       \
        if (tid == 0) {                                                        \
            const uint32_t _mb = mb0 + (s) * 8;                                \
            MBAR_EXPECT_TX(_mb, STG_);                                         \
            BULK_LD(sb + (s) * STG_ + OA,        Asrc + (size_t)(2*(t)) * CHUNK_BYTES,   CHUNK_BYTES, _mb); \
            BULK_LD(sb + (s) * STG_ + OA + 8192, Asrc + (size_t)(2*(t)+1) * CHUNK_BYTES, CHUNK_BYTES, _mb); \
            BULK_LD(sb + (s) * STG_ + OB,        Bsrc + (size_t)(2*(t)) * CHUNK_BYTES,   CHUNK_BYTES, _mb); \
            BULK_LD(sb + (s) * STG_ + OB + 8192, Bsrc + (size_t)(2*(t)+1) * CHUNK_BYTES, CHUNK_BYTES, _mb); \
        }                                                                      \
    } while (0)

    REFILL(0, 0); REFILL(1, 1); REFILL(2, 2);

    float acc[4][4][4];
#pragma unroll
    for (int m = 0; m < 4; m++)
#pragma unroll
        for (int n = 0; n < 4; n++)
#pragma unroll
            for (int r = 0; r < 4; r++) acc[m][n][r] = 0.0f;

    const uint32_t XA = ((lane & 15) >> 1) & 3;
    const uint32_t rowA = (uint32_t)(warp_m * 64 + (lane & 15)) * 64;
    const uint32_t cAsel = (lane >> 4) & 1;
    const uint32_t XB = ((lane & 7) >> 1) & 3;
    const uint32_t rowB = (uint32_t)(warp_n * 32 + ((lane >> 4) & 1) * 8 + (lane & 7)) * 64;
    const uint32_t cBsel = (lane >> 3) & 1;

    int s = 0, ph = 0;
    for (int t = 0; t < NMAC; t++) {
        MBAR_WAIT(mb0 + s * 8, ph);
        const uint32_t stg = sb + s * STG_;
#pragma unroll
        for (int ks = 0; ks < 4; ks++) {
            const uint32_t sub = (ks >> 1) * 8192;
            const uint32_t kk = ks & 1;
            const uint32_t colA = (((kk * 2 + cAsel) ^ XA) << 4);
            const uint32_t colB = (((kk * 2 + cBsel) ^ XB) << 4);
            const uint32_t aBase = stg + OA + sub + rowA + colA;
            const uint32_t bBase = stg + OB + sub + rowB + colB;
            uint32_t a[4][4], b[2][4];
#pragma unroll
            for (int m = 0; m < 4; m++) ldm_x4(aBase + m * 1024, a[m]);
#pragma unroll
            for (int p = 0; p < 2; p++) ldm_x4(bBase + p * 1024, b[p]);
#pragma unroll
            for (int m = 0; m < 4; m++)
#pragma unroll
                for (int n = 0; n < 4; n++)
                    mma16816(acc[m][n], a[m], &b[n >> 1][(n & 1) * 2]);
        }
        __syncthreads();
        if (t + NSTAGE < NMAC) REFILL(t + NSTAGE, s);
        if (++s == NSTAGE) { s = 0; ph ^= 1; }
    }

    // block column maxes
#pragma unroll
    for (int n = 0; n < 4; n++) {
        float m0 = -INFINITY, m1 = -INFINITY;
#pragma unroll
        for (int m = 0; m < 4; m++) {
            m0 = fmaxf(m0, fmaxf(acc[m][n][0], acc[m][n][2]));
            m1 = fmaxf(m1, fmaxf(acc[m][n][1], acc[m][n][3]));
        }
#pragma unroll
        for (int off = 4; off < 32; off <<= 1) {
            m0 = fmaxf(m0, __shfl_xor_sync(0xffffffffu, m0, off));
            m1 = fmaxf(m1, __shfl_xor_sync(0xffffffffu, m1, off));
        }
        if (lane < 4) {
            sred[warp_m][warp_n * 32 + n * 8 + lane * 2 + 0] = m0;
            sred[warp_m][warp_n * 32 + n * 8 + lane * 2 + 1] = m1;
        }
    }
    __syncthreads();
    if (tid < 128) {
        g_qpart[((size_t)pair * 2 + mt) * R_ + nt * 128 + tid] =
            fmaxf(sred[0][tid], sred[1][tid]);
    }
    __syncthreads();

    // candidate emission vs block-local threshold (superset of global)
    const float an = g_anorm_tile[pair * 2 + mt];
    float thr[4][2];
#pragma unroll
    for (int n = 0; n < 4; n++) {
#pragma unroll
        for (int j = 0; j < 2; j++) {
            const int c = warp_n * 32 + n * 8 + (lane & 3) * 2 + j;
            const float bm = fmaxf(sred[0][c], sred[1][c]);
            thr[n][j] = bm - MARGIN_COEF * an * g_wnorm[l * R_ + nt * 128 + c];
        }
    }
#pragma unroll
    for (int m = 0; m < 4; m++)
#pragma unroll
        for (int n = 0; n < 4; n++)
#pragma unroll
            for (int r = 0; r < 4; r++) {
                const int j = r & 1;
                if (acc[m][n][r] >= thr[n][j]) {
                    const int sl = warp_m * 64 + m * 16 + (lane >> 2) + ((r >> 1) << 3);
                    const int gs = mt * 128 + sl;
                    const int gr = nt * 128 + warp_n * 32 + n * 8 + (lane & 3) * 2 + j;
                    const int slot = atomicAdd(&g_ncand, 1);
                    g_cand[slot] = (pair << 16) | (gs << 8) | gr;
                    g_cval[slot] = acc[m][n][r];
                }
            }
#undef REFILL
}

// ---------------- rescue: inline global filter + exact fp32 dot -------------
__global__ void rescue_dot(const float* __restrict__ q_hs,
                           const float* __restrict__ w_q) {
    const int lane = threadIdx.x & 31;
    const int gw = (blockIdx.x * blockDim.x + threadIdx.x) >> 5;
    const int nw = (gridDim.x * blockDim.x) >> 5;
    const int n = g_ncand;
    for (int i = gw; i < n; i += nw) {
        const int id = g_cand[i];
        const int pair = id >> 16, s = (id >> 8) & 255, r = id & 255;
        const int l = pair % L_;
        // global-threshold filter (superset pruning), all lanes redundantly
        const float m_r = fmaxf(g_qpart[((size_t)pair * 2 + 0) * R_ + r],
                                g_qpart[((size_t)pair * 2 + 1) * R_ + r]);
        const float an = fmaxf(g_anorm_tile[pair * 2], g_anorm_tile[pair * 2 + 1]);
        const float thr = m_r - MARGIN_COEF * an * g_wnorm[l * R_ + r];
        if (g_cval[i] < thr) continue;

        const float4* a = (const float4*)(q_hs + ((size_t)pair * 256 + s) * H_);
        const float4* w = (const float4*)(w_q + ((size_t)(l * R_ + r)) * H_);
        float acc = 0.0f;
#pragma unroll 4
        for (int k = lane; k < H_ / 4; k += 32) {
            float4 x = a[k], y = w[k];
            acc += x.x*y.x + x.y*y.y + x.z*y.z + x.w*y.w;
        }
#pragma unroll
        for (int off = 16; off > 0; off >>= 1)
            acc += __shfl_xor_sync(0xffffffffu, acc, off);
        if (lane == 0) atomicMax(&g_qmax[pair * R_ + r], enc_f(acc));
    }
}

// ---------------- normalize ----------------
__global__ void qnorm_kernel() {
    const int row = blockIdx.x;
    const int tid = threadIdx.x;
    float v = dec_f(g_qmax[row * R_ + tid]);
    __shared__ float sm[256];
    sm[tid] = v * v;
    __syncthreads();
    for (int s = 128; s > 0; s >>= 1) {
        if (tid < s) sm[tid] += sm[tid + s];
        __syncthreads();
    }
    float inv = 1.0f / fmaxf(sqrtf(sm[0]), 1e-12f);
    g_qvec[(size_t)row * R_ + tid] = v * inv;
}

// ---------------- doc sims (multi-reduce + chunk prefetch) ----------------
__global__ void __launch_bounds__(256)
docsim_kernel(const float* __restrict__ doc_keys) {
    const int d = blockIdx.x;
    const int l = blockIdx.y;
    const int tid = threadIdx.x;

    __shared__ float4 qs[B_ * 64];
    for (int i = tid; i < B_ * 64; i += 256) {
        int b = i >> 6, j = i & 63;
        qs[i] = *(const float4*)&g_qvec[((size_t)(b * L_ + l)) * R_ + j * 4];
    }
    __syncthreads();

    const int w = tid >> 5, lane = tid & 31;
    float bmax_l = -INFINITY;

    const float* kb = doc_keys + ((size_t)(d * L_ + l)) * C_ * R_;
    const float4* kp0 = (const float4*)(kb + (size_t)(w * 4) * R_);
    float4 k0 = kp0[lane], k1 = kp0[lane + 32];

    for (int ci = 0; ci < 4; ci++) {
        float4 n0, n1;
        if (ci < 3) {
            const float4* np = (const float4*)(kb + (size_t)(w * 4 + ci + 1) * R_);
            n0 = np[lane]; n1 = np[lane + 32];
        }

        float n2 = k0.x*k0.x + k0.y*k0.y + k0.z*k0.z + k0.w*k0.w +
                   k1.x*k1.x + k1.y*k1.y + k1.z*k1.z + k1.w*k1.w;
#pragma unroll
        for (int off = 16; off > 0; off >>= 1) n2 += __shfl_xor_sync(0xffffffffu, n2, off);
        const float inv = 1.0f / fmaxf(sqrtf(n2), 1e-12f);

        float p[16];
#pragma unroll
        for (int b = 0; b < 16; b++) {
            float4 q0 = qs[b * 64 + lane], q1 = qs[b * 64 + 32 + lane];
            p[b] = k0.x*q0.x + k0.y*q0.y + k0.z*q0.z + k0.w*q0.w +
                   k1.x*q1.x + k1.y*q1.y + k1.z*q1.z + k1.w*q1.w;
        }
#pragma unroll
        for (int b = 0; b < 16; b++) p[b] += __shfl_xor_sync(0xffffffffu, p[b], 16);
#pragma unroll
        for (int bit = 3; bit >= 0; bit--) {
            const int half = 1 << bit;
            const int sel = (lane >> bit) & 1;
#pragma unroll
            for (int j = 0; j < 8; j++) {
                if (j < half) {
                    float keep = sel ? p[j + half] : p[j];
                    float send = sel ? p[j] : p[j + half];
                    float recv = __shfl_xor_sync(0xffffffffu, send, 1 << bit);
                    p[j] = keep + recv;
                }
            }
        }
        bmax_l = fmaxf(bmax_l, p[0] * inv);

        if (ci < 3) { k0 = n0; k1 = n1; }
    }

    __shared__ float red[8][16];
    if (lane < 16) red[w][lane] = bmax_l;
    __syncthreads();
    if (tid < 16) {
        float m = red[0][tid];
#pragma unroll
        for (int i = 1; i < 8; i++) m = fmaxf(m, red[i][tid]);
        g_sims[((size_t)(tid * D_ + d)) * L_ + l] = m;
    }
}

// ---------------- top-k ----------------
__global__ void topk_kernel(float* __restrict__ out, int out_size) {
    const int b = blockIdx.x;
    const int tid = threadIdx.x;
    __shared__ float sv[D_];
    for (int i = tid; i < D_; i += 256) {
        const float* p = &g_sims[((size_t)(b * D_ + i)) * L_];
        float ssum = 0.0f;
#pragma unroll
        for (int l = 0; l < L_; l++) ssum += p[l];
        sv[i] = ssum / (float)L_;
    }
    __syncthreads();
    __shared__ float rv[256];
    __shared__ int ri[256];
    for (int k = 0; k < TOPK_; k++) {
        float best = -INFINITY; int bi = 0x7fffffff;
        for (int i = tid; i < D_; i += 256) {
            float v = sv[i];
            if (v > best || (v == best && i < bi)) { best = v; bi = i; }
        }
        rv[tid] = best; ri[tid] = bi;
        __syncthreads();
        for (int s = 128; s > 0; s >>= 1) {
            if (tid < s) {
                float v2 = rv[tid + s]; int i2 = ri[tid + s];
                if (v2 > rv[tid] || (v2 == rv[tid] && i2 < ri[tid])) { rv[tid] = v2; ri[tid] = i2; }
            }
            __syncthreads();
        }
        if (tid == 0) {
            out[b * TOPK_ + k] = rv[0];
            if (out_size >= 2 * B_ * TOPK_) out[B_ * TOPK_ + b * TOPK_ + k] = (float)ri[0];
            sv[ri[0]] = -INFINITY;
        }
        __syncthreads();
    }
}

// ---------------------------------------------------------------------------
extern "C" void kernel_launch(void* const* d_in, const int* in_sizes, int n_in,
                              void* d_out, int out_size) {
    const float* q_hs     = (const float*)d_in[0];
    const float* w_q      = (const float*)d_in[1];
    const float* doc_keys = (const float*)d_in[2];
    (void)in_sizes; (void)n_in;

    cudaFuncSetAttribute(qproj_mma, cudaFuncAttributeMaxDynamicSharedMemorySize, QP_DSM);

    pack_w_kernel<<<L_ * 2, 256>>>(w_q);          // resets counter
    pack_a_kernel<<<B_ * L_ * 2, 256>>>(q_hs);    // inits g_qmax
    dim3 gA(4, B_ * L_);
    qproj_mma<<<gA, 256, QP_DSM>>>();
    rescue_dot<<<2048, 256>>>(q_hs, w_q);
    qnorm_kernel<<<B_ * L_, 256>>>();
    dim3 gB(D_, L_);
    docsim_kernel<<<gB, 256>>>(doc_keys);
    topk_kernel<<<B_, 256>>>((float*)d_out, out_size);
}

// round 17
// speedup vs baseline: 1.4814x; 1.0175x over previous
#include <cuda_runtime.h>
#include <cuda_bf16.h>
#include <math.h>
#include <stdint.h>

#define B_   16
#define L_   18
#define SQ_  256
#define H_   2560
#define R_   256
#define D_   2048
#define C_   32
#define TOPK_ 16

#define NCHK 80              // H/32 packed chunks
#define CHUNK_BYTES 8192     // 128 rows x 64B bf16
#define TILE_STRIDE (NCHK * CHUNK_BYTES)
#define MAXCAND (B_ * L_ * SQ_ * R_)

__device__ float g_qpart[2 * B_ * L_ * R_];
__device__ unsigned g_qmax[B_ * L_ * R_];
__device__ float g_qvec[B_ * L_ * R_];
__device__ float g_sims[B_ * D_ * L_];
__device__ float g_anorm_tile[B_ * L_ * 2];
__device__ float g_wnorm[L_ * R_];
__device__ int   g_ncand;
__device__ int   g_cand[MAXCAND];
__device__ float g_cval[MAXCAND];
__device__ __align__(16) uint8_t g_apack[B_ * L_ * 2 * TILE_STRIDE];
__device__ __align__(16) uint8_t g_wpack[L_ * 2 * TILE_STRIDE];

// combined 2-sided bf16-dot error: sigma ~ sqrt(2)*2^-8*||a||*||w||/sqrt(H)
// ~= 1.1e-4 * an*wn;  0.0012 ~ 11 sigma (miss prob ~2e-28/col)
#define MARGIN_COEF 0.0012f

// ---------------- helpers ----------------
__device__ __forceinline__ uint32_t smem_u32(const void* p) {
    uint32_t a;
    asm("{ .reg .u64 t; cvta.to.shared.u64 t, %1; cvt.u32.u64 %0, t; }" : "=r"(a) : "l"(p));
    return a;
}
#define MBAR_INIT(a, c) asm volatile("mbarrier.init.shared.b64 [%0], %1;" :: "r"(a), "r"(c) : "memory")
#define MBAR_EXPECT_TX(a, n) asm volatile("mbarrier.arrive.expect_tx.shared.b64 _, [%0], %1;" :: "r"(a), "r"(n) : "memory")
#define MBAR_WAIT(a, par) do {                                                  \
    uint32_t _m=(a), _p=(par), _d;                                              \
    asm volatile("{\n\t.reg .pred p;\n\t"                                       \
      "mbarrier.try_wait.parity.acquire.cta.shared::cta.b64 p, [%1], %2;\n\t"   \
      "selp.b32 %0,1,0,p;\n\t}" : "=r"(_d) : "r"(_m), "r"(_p) : "memory");      \
    if (!_d) { asm volatile("{\n\t.reg .pred P1;\n\tW_%=:\n\t"                  \
      "mbarrier.try_wait.parity.acquire.cta.shared::cta.b64 P1, [%0], %1, 0x989680;\n\t" \
      "@P1 bra.uni WD_%=;\n\tbra.uni W_%=;\n\tWD_%=:\n\t}" :: "r"(_m), "r"(_p) : "memory"); } \
} while (0)
#define BULK_LD(dst, src, sz, mb) \
    asm volatile("cp.async.bulk.shared::cluster.global.mbarrier::complete_tx::bytes [%0], [%1], %2, [%3];" \
                 :: "r"(dst), "l"(src), "r"(sz), "r"(mb) : "memory")

__device__ __forceinline__ void ldm_x4(uint32_t a, uint32_t* r) {
    asm volatile("ldmatrix.sync.aligned.m8n8.x4.shared.b16 {%0,%1,%2,%3}, [%4];"
        : "=r"(r[0]), "=r"(r[1]), "=r"(r[2]), "=r"(r[3]) : "r"(a));
}
__device__ __forceinline__ void mma16816(float* c, const uint32_t* a, const uint32_t* b) {
    asm volatile("mma.sync.aligned.m16n8k16.row.col.f32.bf16.bf16.f32 "
        "{%0,%1,%2,%3}, {%4,%5,%6,%7}, {%8,%9}, {%0,%1,%2,%3};"
        : "+f"(c[0]), "+f"(c[1]), "+f"(c[2]), "+f"(c[3])
        : "r"(a[0]), "r"(a[1]), "r"(a[2]), "r"(a[3]), "r"(b[0]), "r"(b[1]));
}
__device__ __forceinline__ unsigned enc_f(float f) {
    unsigned u = __float_as_uint(f);
    return (u & 0x80000000u) ? ~u : (u | 0x80000000u);
}
__device__ __forceinline__ float dec_f(unsigned u) {
    unsigned v = (u & 0x80000000u) ? (u & 0x7fffffffu) : ~u;
    return __uint_as_float(v);
}

// stage = 2 A-chunks (16KB) + 2 B-chunks (16KB) = 32KB; 3 stages = 96KB
#define OA 0
#define OB 16384
#define STG_ 32768
#define NSTAGE 3
#define NMAC 40              // macro chunks of K=64
#define QP_DSM (NSTAGE * STG_)

// ---------------- pack kernels: fp32 -> bf16 chunk tiles + L2 norms ---------
__device__ __forceinline__ void pack_half_chunk(const float* __restrict__ s,
                                                uint8_t* __restrict__ dstc,
                                                int h, uint32_t X, float& nrm) {
#pragma unroll
    for (int j = 0; j < 2; j++) {
        float4 a = ((const float4*)s)[j * 2];
        float4 b = ((const float4*)s)[j * 2 + 1];
        nrm += a.x*a.x + a.y*a.y + a.z*a.z + a.w*a.w +
               b.x*b.x + b.y*b.y + b.z*b.z + b.w*b.w;
        __nv_bfloat162 p0 = __floats2bfloat162_rn(a.x, a.y);
        __nv_bfloat162 p1 = __floats2bfloat162_rn(a.z, a.w);
        __nv_bfloat162 p2 = __floats2bfloat162_rn(b.x, b.y);
        __nv_bfloat162 p3 = __floats2bfloat162_rn(b.z, b.w);
        uint4 out = make_uint4(*(uint32_t*)&p0, *(uint32_t*)&p1,
                               *(uint32_t*)&p2, *(uint32_t*)&p3);
        const uint32_t g = h * 2 + j;
        *(uint4*)(dstc + (((g ^ X) << 4))) = out;
    }
}

__global__ void pack_a_kernel(const float* __restrict__ q_hs) {
    const int tile = blockIdx.x;
    const int tid = threadIdx.x;
    const int row = tid >> 1, h = tid & 1;
    if ((tile & 1) == 0) g_qmax[(tile >> 1) * R_ + tid] = enc_f(-INFINITY);
    const float* src = q_hs + ((size_t)tile * 128 + row) * H_;
    uint8_t* dst = g_apack + (size_t)tile * TILE_STRIDE + row * 64;
    const uint32_t X = (row >> 1) & 3;
    float nrm = 0.0f;
    for (int c = 0; c < NCHK; c++)
        pack_half_chunk(src + c * 32 + h * 16, dst + (size_t)c * CHUNK_BYTES, h, X, nrm);
    nrm += __shfl_xor_sync(0xffffffffu, nrm, 1);
    __shared__ float sm[256];
    sm[tid] = nrm;
    __syncthreads();
    for (int s = 128; s > 0; s >>= 1) {
        if (tid < s) sm[tid] = fmaxf(sm[tid], sm[tid + s]);
        __syncthreads();
    }
    if (tid == 0) g_anorm_tile[tile] = sqrtf(sm[0]);
}

__global__ void pack_w_kernel(const float* __restrict__ w_q) {
    const int tile = blockIdx.x;
    const int l = tile >> 1, nt = tile & 1;
    const int tid = threadIdx.x;
    const int row = tid >> 1, h = tid & 1;
    if (tile == 0 && tid == 0) g_ncand = 0;
    const float* src = w_q + ((size_t)(l * R_ + nt * 128 + row)) * H_;
    uint8_t* dst = g_wpack + (size_t)tile * TILE_STRIDE + row * 64;
    const uint32_t X = (row >> 1) & 3;
    float nrm = 0.0f;
    for (int c = 0; c < NCHK; c++)
        pack_half_chunk(src + c * 32 + h * 16, dst + (size_t)c * CHUNK_BYTES, h, X, nrm);
    nrm += __shfl_xor_sync(0xffffffffu, nrm, 1);
    if (h == 0) g_wnorm[l * R_ + nt * 128 + row] = sqrtf(nrm);
}

// ---------------- bf16 GEMM (K-macro 64) + max-pool + candidate emission ----
__global__ void __launch_bounds__(256, 2) qproj_mma() {
    extern __shared__ char dsm[];
    __shared__ float sred[2][128];
    __shared__ uint64_t mbars[NSTAGE];

    const uint32_t sb = smem_u32(dsm);
    const int mt = blockIdx.x & 1;
    const int nt = blockIdx.x >> 1;
    const int pair = blockIdx.y;
    const int l = pair % L_;

    const int tid = threadIdx.x;
    const int wid = tid >> 5;
    const int lane = tid & 31;
    const int warp_m = wid >> 2;
    const int warp_n = wid & 3;

    const uint8_t* Asrc = g_apack + (size_t)(pair * 2 + mt) * TILE_STRIDE;
    const uint8_t* Bsrc = g_wpack + (size_t)(l * 2 + nt) * TILE_STRIDE;

    const uint32_t mb0 = smem_u32(&mbars[0]);
    if (tid == 0) {
#pragma unroll
        for (int i = 0; i < NSTAGE; i++) MBAR_INIT(mb0 + i * 8, 1);
    }
    __syncthreads();

#define REFILL(t, s)                                                           \
    do {                                                                       \
        if (tid == 0) {                                                        \
            const uint32_t _mb = mb0 + (s) * 8;                                \
            MBAR_EXPECT_TX(_mb, STG_);                                         \
            BULK_LD(sb + (s) * STG_ + OA,        Asrc + (size_t)(2*(t)) * CHUNK_BYTES,   CHUNK_BYTES, _mb); \
            BULK_LD(sb + (s) * STG_ + OA + 8192, Asrc + (size_t)(2*(t)+1) * CHUNK_BYTES, CHUNK_BYTES, _mb); \
            BULK_LD(sb + (s) * STG_ + OB,        Bsrc + (size_t)(2*(t)) * CHUNK_BYTES,   CHUNK_BYTES, _mb); \
            BULK_LD(sb + (s) * STG_ + OB + 8192, Bsrc + (size_t)(2*(t)+1) * CHUNK_BYTES, CHUNK_BYTES, _mb); \
        }                                                                      \
    } while (0)

    REFILL(0, 0); REFILL(1, 1); REFILL(2, 2);

    float acc[4][4][4];
#pragma unroll
    for (int m = 0; m < 4; m++)
#pragma unroll
        for (int n = 0; n < 4; n++)
#pragma unroll
            for (int r = 0; r < 4; r++) acc[m][n][r] = 0.0f;

    const uint32_t XA = ((lane & 15) >> 1) & 3;
    const uint32_t rowA = (uint32_t)(warp_m * 64 + (lane & 15)) * 64;
    const uint32_t cAsel = (lane >> 4) & 1;
    const uint32_t XB = ((lane & 7) >> 1) & 3;
    const uint32_t rowB = (uint32_t)(warp_n * 32 + ((lane >> 4) & 1) * 8 + (lane & 7)) * 64;
    const uint32_t cBsel = (lane >> 3) & 1;

    int s = 0, ph = 0;
    for (int t = 0; t < NMAC; t++) {
        MBAR_WAIT(mb0 + s * 8, ph);
        const uint32_t stg = sb + s * STG_;
#pragma unroll
        for (int ks = 0; ks < 4; ks++) {
            const uint32_t sub = (ks >> 1) * 8192;
            const uint32_t kk = ks & 1;
            const uint32_t colA = (((kk * 2 + cAsel) ^ XA) << 4);
            const uint32_t colB = (((kk * 2 + cBsel) ^ XB) << 4);
            const uint32_t aBase = stg + OA + sub + rowA + colA;
            const uint32_t bBase = stg + OB + sub + rowB + colB;
            uint32_t a[4][4], b[2][4];
#pragma unroll
            for (int m = 0; m < 4; m++) ldm_x4(aBase + m * 1024, a[m]);
#pragma unroll
            for (int p = 0; p < 2; p++) ldm_x4(bBase + p * 1024, b[p]);
#pragma unroll
            for (int m = 0; m < 4; m++)
#pragma unroll
                for (int n = 0; n < 4; n++)
                    mma16816(acc[m][n], a[m], &b[n >> 1][(n & 1) * 2]);
        }
        __syncthreads();
        if (t + NSTAGE < NMAC) REFILL(t + NSTAGE, s);
        if (++s == NSTAGE) { s = 0; ph ^= 1; }
    }

    // block column maxes
#pragma unroll
    for (int n = 0; n < 4; n++) {
        float m0 = -INFINITY, m1 = -INFINITY;
#pragma unroll
        for (int m = 0; m < 4; m++) {
            m0 = fmaxf(m0, fmaxf(acc[m][n][0], acc[m][n][2]));
            m1 = fmaxf(m1, fmaxf(acc[m][n][1], acc[m][n][3]));
        }
#pragma unroll
        for (int off = 4; off < 32; off <<= 1) {
            m0 = fmaxf(m0, __shfl_xor_sync(0xffffffffu, m0, off));
            m1 = fmaxf(m1, __shfl_xor_sync(0xffffffffu, m1, off));
        }
        if (lane < 4) {
            sred[warp_m][warp_n * 32 + n * 8 + lane * 2 + 0] = m0;
            sred[warp_m][warp_n * 32 + n * 8 + lane * 2 + 1] = m1;
        }
    }
    __syncthreads();
    if (tid < 128) {
        g_qpart[((size_t)pair * 2 + mt) * R_ + nt * 128 + tid] =
            fmaxf(sred[0][tid], sred[1][tid]);
    }
    __syncthreads();

    // candidate emission vs block-local threshold (superset of global)
    const float an = g_anorm_tile[pair * 2 + mt];
    float thr[4][2];
#pragma unroll
    for (int n = 0; n < 4; n++) {
#pragma unroll
        for (int j = 0; j < 2; j++) {
            const int c = warp_n * 32 + n * 8 + (lane & 3) * 2 + j;
            const float bm = fmaxf(sred[0][c], sred[1][c]);
            thr[n][j] = bm - MARGIN_COEF * an * g_wnorm[l * R_ + nt * 128 + c];
        }
    }
#pragma unroll
    for (int m = 0; m < 4; m++)
#pragma unroll
        for (int n = 0; n < 4; n++)
#pragma unroll
            for (int r = 0; r < 4; r++) {
                const int j = r & 1;
                if (acc[m][n][r] >= thr[n][j]) {
                    const int sl = warp_m * 64 + m * 16 + (lane >> 2) + ((r >> 1) << 3);
                    const int gs = mt * 128 + sl;
                    const int gr = nt * 128 + warp_n * 32 + n * 8 + (lane & 3) * 2 + j;
                    const int slot = atomicAdd(&g_ncand, 1);
                    g_cand[slot] = (pair << 16) | (gs << 8) | gr;
                    g_cval[slot] = acc[m][n][r];
                }
            }
#undef REFILL
}

// ---------------- rescue: inline global filter + exact fp32 dot -------------
__global__ void rescue_dot(const float* __restrict__ q_hs,
                           const float* __restrict__ w_q) {
    const int lane = threadIdx.x & 31;
    const int gw = (blockIdx.x * blockDim.x + threadIdx.x) >> 5;
    const int nw = (gridDim.x * blockDim.x) >> 5;
    const int n = g_ncand;
    for (int i = gw; i < n; i += nw) {
        const int id = g_cand[i];
        const int pair = id >> 16, s = (id >> 8) & 255, r = id & 255;
        const int l = pair % L_;
        const float m_r = fmaxf(g_qpart[((size_t)pair * 2 + 0) * R_ + r],
                                g_qpart[((size_t)pair * 2 + 1) * R_ + r]);
        const float an = fmaxf(g_anorm_tile[pair * 2], g_anorm_tile[pair * 2 + 1]);
        const float thr = m_r - MARGIN_COEF * an * g_wnorm[l * R_ + r];
        if (g_cval[i] < thr) continue;

        const float4* a = (const float4*)(q_hs + ((size_t)pair * 256 + s) * H_);
        const float4* w = (const float4*)(w_q + ((size_t)(l * R_ + r)) * H_);
        float acc = 0.0f;
#pragma unroll 4
        for (int k = lane; k < H_ / 4; k += 32) {
            float4 x = a[k], y = w[k];
            acc += x.x*y.x + x.y*y.y + x.z*y.z + x.w*y.w;
        }
#pragma unroll
        for (int off = 16; off > 0; off >>= 1)
            acc += __shfl_xor_sync(0xffffffffu, acc, off);
        if (lane == 0) atomicMax(&g_qmax[pair * R_ + r], enc_f(acc));
    }
}

// ---------------- normalize ----------------
__global__ void qnorm_kernel() {
    const int row = blockIdx.x;
    const int tid = threadIdx.x;
    float v = dec_f(g_qmax[row * R_ + tid]);
    __shared__ float sm[256];
    sm[tid] = v * v;
    __syncthreads();
    for (int s = 128; s > 0; s >>= 1) {
        if (tid < s) sm[tid] += sm[tid + s];
        __syncthreads();
    }
    float inv = 1.0f / fmaxf(sqrtf(sm[0]), 1e-12f);
    g_qvec[(size_t)row * R_ + tid] = v * inv;
}

// ---------------- doc sims (multi-reduce + chunk prefetch) ----------------
__global__ void __launch_bounds__(256)
docsim_kernel(const float* __restrict__ doc_keys) {
    const int d = blockIdx.x;
    const int l = blockIdx.y;
    const int tid = threadIdx.x;

    __shared__ float4 qs[B_ * 64];
    for (int i = tid; i < B_ * 64; i += 256) {
        int b = i >> 6, j = i & 63;
        qs[i] = *(const float4*)&g_qvec[((size_t)(b * L_ + l)) * R_ + j * 4];
    }
    __syncthreads();

    const int w = tid >> 5, lane = tid & 31;
    float bmax_l = -INFINITY;

    const float* kb = doc_keys + ((size_t)(d * L_ + l)) * C_ * R_;
    const float4* kp0 = (const float4*)(kb + (size_t)(w * 4) * R_);
    float4 k0 = kp0[lane], k1 = kp0[lane + 32];

    for (int ci = 0; ci < 4; ci++) {
        float4 n0, n1;
        if (ci < 3) {
            const float4* np = (const float4*)(kb + (size_t)(w * 4 + ci + 1) * R_);
            n0 = np[lane]; n1 = np[lane + 32];
        }

        float n2 = k0.x*k0.x + k0.y*k0.y + k0.z*k0.z + k0.w*k0.w +
                   k1.x*k1.x + k1.y*k1.y + k1.z*k1.z + k1.w*k1.w;
#pragma unroll
        for (int off = 16; off > 0; off >>= 1) n2 += __shfl_xor_sync(0xffffffffu, n2, off);
        const float inv = 1.0f / fmaxf(sqrtf(n2), 1e-12f);

        float p[16];
#pragma unroll
        for (int b = 0; b < 16; b++) {
            float4 q0 = qs[b * 64 + lane], q1 = qs[b * 64 + 32 + lane];
            p[b] = k0.x*q0.x + k0.y*q0.y + k0.z*q0.z + k0.w*q0.w +
                   k1.x*q1.x + k1.y*q1.y + k1.z*q1.z + k1.w*q1.w;
        }
#pragma unroll
        for (int b = 0; b < 16; b++) p[b] += __shfl_xor_sync(0xffffffffu, p[b], 16);
#pragma unroll
        for (int bit = 3; bit >= 0; bit--) {
            const int half = 1 << bit;
            const int sel = (lane >> bit) & 1;
#pragma unroll
            for (int j = 0; j < 8; j++) {
                if (j < half) {
                    float keep = sel ? p[j + half] : p[j];
                    float send = sel ? p[j] : p[j + half];
                    float recv = __shfl_xor_sync(0xffffffffu, send, 1 << bit);
                    p[j] = keep + recv;
                }
            }
        }
        bmax_l = fmaxf(bmax_l, p[0] * inv);

        if (ci < 3) { k0 = n0; k1 = n1; }
    }

    __shared__ float red[8][16];
    if (lane < 16) red[w][lane] = bmax_l;
    __syncthreads();
    if (tid < 16) {
        float m = red[0][tid];
#pragma unroll
        for (int i = 1; i < 8; i++) m = fmaxf(m, red[i][tid]);
        g_sims[((size_t)(tid * D_ + d)) * L_ + l] = m;
    }
}

// ---------------- top-k ----------------
__global__ void topk_kernel(float* __restrict__ out, int out_size) {
    const int b = blockIdx.x;
    const int tid = threadIdx.x;
    __shared__ float sv[D_];
    for (int i = tid; i < D_; i += 256) {
        const float* p = &g_sims[((size_t)(b * D_ + i)) * L_];
        float ssum = 0.0f;
#pragma unroll
        for (int l = 0; l < L_; l++) ssum += p[l];
        sv[i] = ssum / (float)L_;
    }
    __syncthreads();
    __shared__ float rv[256];
    __shared__ int ri[256];
    for (int k = 0; k < TOPK_; k++) {
        float best = -INFINITY; int bi = 0x7fffffff;
        for (int i = tid; i < D_; i += 256) {
            float v = sv[i];
            if (v > best || (v == best && i < bi)) { best = v; bi = i; }
        }
        rv[tid] = best; ri[tid] = bi;
        __syncthreads();
        for (int s = 128; s > 0; s >>= 1) {
            if (tid < s) {
                float v2 = rv[tid + s]; int i2 = ri[tid + s];
                if (v2 > rv[tid] || (v2 == rv[tid] && i2 < ri[tid])) { rv[tid] = v2; ri[tid] = i2; }
            }
            __syncthreads();
        }
        if (tid == 0) {
            out[b * TOPK_ + k] = rv[0];
            if (out_size >= 2 * B_ * TOPK_) out[B_ * TOPK_ + b * TOPK_ + k] = (float)ri[0];
            sv[ri[0]] = -INFINITY;
        }
        __syncthreads();
    }
}

// ---------------------------------------------------------------------------
extern "C" void kernel_launch(void* const* d_in, const int* in_sizes, int n_in,
                              void* d_out, int out_size) {
    const float* q_hs     = (const float*)d_in[0];
    const float* w_q      = (const float*)d_in[1];
    const float* doc_keys = (const float*)d_in[2];
    (void)in_sizes; (void)n_in;

    cudaFuncSetAttribute(qproj_mma, cudaFuncAttributeMaxDynamicSharedMemorySize, QP_DSM);

    pack_w_kernel<<<L_ * 2, 256>>>(w_q);          // resets counter
    pack_a_kernel<<<B_ * L_ * 2, 256>>>(q_hs);    // inits g_qmax
    dim3 gA(4, B_ * L_);
    qproj_mma<<<gA, 256, QP_DSM>>>();
    rescue_dot<<<2048, 256>>>(q_hs, w_q);
    qnorm_kernel<<<B_ * L_, 256>>>();
    dim3 gB(D_, L_);
    docsim_kernel<<<gB, 256>>>(doc_keys);
    topk_kernel<<<B_, 256>>>((float*)d_out, out_size);
}